// round 6
// baseline (speedup 1.0000x reference)
#include <cuda_runtime.h>
#include <cuda_fp16.h>
#include <cstdint>

#define BATCH 128
#define SEQ   512
#define HID   1024
#define H2    2048
#define EMB   512
#define VOCAB 32000
#define KG    3584
#define NG    4096
#define K1G   2560          /* W_ih K extent */
#define GSPLIT 4
#define ASPLIT 4
#define ROWS_PER_CTA (SEQ / ASPLIT)        /* 128 */
#define TILE_ROWS 4
#define NTILES (ROWS_PER_CTA / TILE_ROWS)  /* 32 */
#define ROWB  (H2 * 4)                     /* 8192 B per enc row */
#define BUFB  (TILE_ROWS * ROWB)           /* 32 KB per tile buffer */
#define ATTN_SMEM (2 * BUFB)               /* 64 KB dynamic */
#define PADK  24                           /* halfs per 16-elem row (48B stride) */
#define STG   ((64 + 256) * PADK)          /* 7680 halfs per stage */

__device__ float  g_ctx_part[ASPLIT * BATCH * H2];
__device__ float  g_zpart[ASPLIT * BATCH];
__device__ __half g_act16[BATCH * KG];      // [ctx | emb | hidden] fp16
__device__ __half g_h16[BATCH * HID];       // h_new fp16
__device__ float  g_gates_part[GSPLIT * BATCH * NG];

// ---------------------------------------------------------------------------
// PTX helpers
// ---------------------------------------------------------------------------
__device__ __forceinline__ uint32_t smem_u32(const void* p) {
    return (uint32_t)__cvta_generic_to_shared(p);
}
__device__ __forceinline__ void cpa16(uint32_t dst, const void* src) {
    asm volatile("cp.async.cg.shared.global [%0], [%1], 16;\n" :: "r"(dst), "l"(src));
}
#define CPA_COMMIT() asm volatile("cp.async.commit_group;\n" ::: "memory")
#define CPA_WAIT(n)  asm volatile("cp.async.wait_group %0;\n" :: "n"(n) : "memory")

__device__ __forceinline__ void ldm_x4(uint32_t* r, const __half* p) {
    uint32_t a = smem_u32(p);
    asm volatile("ldmatrix.sync.aligned.m8n8.x4.shared.b16 {%0,%1,%2,%3}, [%4];\n"
                 : "=r"(r[0]), "=r"(r[1]), "=r"(r[2]), "=r"(r[3]) : "r"(a));
}
__device__ __forceinline__ void mma_f16(float* d, const uint32_t* a, const uint32_t* b) {
    asm volatile("mma.sync.aligned.m16n8k16.row.col.f32.f16.f16.f32 "
                 "{%0,%1,%2,%3}, {%4,%5,%6,%7}, {%8,%9}, {%0,%1,%2,%3};\n"
                 : "+f"(d[0]), "+f"(d[1]), "+f"(d[2]), "+f"(d[3])
                 : "r"(a[0]), "r"(a[1]), "r"(a[2]), "r"(a[3]), "r"(b[0]), "r"(b[1]));
}
__device__ __forceinline__ uint32_t pk(float a, float b) {
    __half2 h = __floats2half2_rn(a, b);
    return *reinterpret_cast<uint32_t*>(&h);
}

// ===========================================================================
// attention: grid (BATCH, ASPLIT), 256 thr, occ 2. cp.async smem tile
// pipeline (4 rows x 8KB, double buffered). Warp w dots half-row (w&1) of
// row (w>>1); acc phase: thread owns 8 features across all 4 tile rows.
// Unnormalized partial context + partial Z per (b, split).
// ===========================================================================
extern __shared__ char s_dyn[];

__global__ __launch_bounds__(256, 2) void attn_kernel(
    const float* __restrict__ enc, const float* __restrict__ hidden,
    const float* __restrict__ W_e, const float* __restrict__ b_e)
{
    __shared__ float s_pd[8], s_red[8];
    __shared__ float s_hb;

    int b = blockIdx.x, split = blockIdx.y, t = threadIdx.x;
    int warp = t >> 5, lane = t & 31;
    int row = warp >> 1, half = warp & 1;
    uint32_t sb = smem_u32(s_dyn);

    // hb = hidden[b] . W_e[0:HID] + b_e
    float p = 0.f;
    for (int j = t; j < HID; j += 256) p += hidden[b * HID + j] * W_e[j];
    #pragma unroll
    for (int o = 16; o > 0; o >>= 1) p += __shfl_xor_sync(0xffffffffu, p, o);
    if (lane == 0) s_red[warp] = p;
    __syncthreads();
    if (t == 0) {
        float s = 0.f;
        #pragma unroll
        for (int i = 0; i < 8; i++) s += s_red[i];
        s_hb = s + b_e[0];
    }
    __syncthreads();
    float hb = s_hb;

    // this thread's w2 slice (for the half-row dot)
    float4 w2r[8];
    #pragma unroll
    for (int i = 0; i < 8; i++)
        w2r[i] = *(const float4*)(W_e + HID + half * 1024 + lane * 4 + i * 128);

    float4 acc0 = make_float4(0.f, 0.f, 0.f, 0.f);
    float4 acc1 = make_float4(0.f, 0.f, 0.f, 0.f);
    float Z = 0.f;
    int s0 = split * ROWS_PER_CTA;

    auto issue_tile = [&](int tile, int buf) {
        const char* src = (const char*)(enc +
            ((size_t)(s0 + tile * TILE_ROWS + row) * BATCH + b) * H2) +
            half * 4096 + lane * 16;
        uint32_t dst = sb + buf * BUFB + row * ROWB + half * 4096 + lane * 16;
        #pragma unroll
        for (int c = 0; c < 8; c++) cpa16(dst + c * 512, src + c * 512);
        CPA_COMMIT();
    };

    issue_tile(0, 0);

    for (int tile = 0; tile < NTILES; tile++) {
        int cur = tile & 1;
        if (tile + 1 < NTILES) {
            issue_tile(tile + 1, cur ^ 1);
            CPA_WAIT(1);
        } else {
            CPA_WAIT(0);
        }
        __syncthreads();                       // all rows of tile landed

        // dot: warp dots its half-row
        const char* mybuf = s_dyn + cur * BUFB;
        {
            const float4* rp = (const float4*)(mybuf + row * ROWB + half * 4096) + lane;
            float pr = 0.f;
            #pragma unroll
            for (int i = 0; i < 8; i++) {
                float4 v = rp[i * 32];
                float4 w = w2r[i];
                pr += v.x * w.x + v.y * w.y + v.z * w.z + v.w * w.w;
            }
            #pragma unroll
            for (int o = 16; o > 0; o >>= 1) pr += __shfl_xor_sync(0xffffffffu, pr, o);
            if (lane == 0) s_pd[warp] = pr;
        }
        __syncthreads();                       // partial dots visible

        float wg[TILE_ROWS];
        #pragma unroll
        for (int r = 0; r < TILE_ROWS; r++) {
            float e = fmaxf(s_pd[2 * r] + s_pd[2 * r + 1] + hb, 0.f);
            wg[r] = __expf(e);
            Z += wg[r];
        }

        // acc: thread owns features [t*8, t*8+8)
        #pragma unroll
        for (int r = 0; r < TILE_ROWS; r++) {
            float4 v0 = *(const float4*)(mybuf + r * ROWB + t * 32);
            float4 v1 = *(const float4*)(mybuf + r * ROWB + t * 32 + 16);
            acc0.x += wg[r] * v0.x; acc0.y += wg[r] * v0.y;
            acc0.z += wg[r] * v0.z; acc0.w += wg[r] * v0.w;
            acc1.x += wg[r] * v1.x; acc1.y += wg[r] * v1.y;
            acc1.z += wg[r] * v1.z; acc1.w += wg[r] * v1.w;
        }
        __syncthreads();                       // done reading cur before reissue
    }

    float* dst = g_ctx_part + ((size_t)split * BATCH + b) * H2 + t * 8;
    *(float4*)(dst)     = acc0;
    *(float4*)(dst + 4) = acc1;
    if (t == 0) g_zpart[split * BATCH + b] = Z;   // identical across threads
}

// ===========================================================================
// pack: merge ASPLIT partial contexts, normalize, cvt fp16; append emb+hidden
// ===========================================================================
__global__ __launch_bounds__(256) void pack_kernel(
    const int* __restrict__ x, const float* __restrict__ emb_table,
    const float* __restrict__ hidden)
{
    int b = blockIdx.x, t = threadIdx.x;
    float z = g_zpart[b] + g_zpart[BATCH + b] + g_zpart[2 * BATCH + b] + g_zpart[3 * BATCH + b];
    float iz = 1.f / z;
    __half* dst = g_act16 + (size_t)b * KG;

    for (int f = 4 * t; f < H2; f += 1024) {
        float4 s = *(const float4*)(g_ctx_part + (size_t)b * H2 + f);
        #pragma unroll
        for (int sp = 1; sp < ASPLIT; sp++) {
            float4 q = *(const float4*)(g_ctx_part + ((size_t)sp * BATCH + b) * H2 + f);
            s.x += q.x; s.y += q.y; s.z += q.z; s.w += q.w;
        }
        uint2 o = make_uint2(pk(s.x * iz, s.y * iz), pk(s.z * iz, s.w * iz));
        *(uint2*)(dst + f) = o;
    }
    int tok = x[b];
    for (int f = 4 * t; f < EMB; f += 1024) {
        float4 e = *(const float4*)(emb_table + (size_t)tok * EMB + f);
        *(uint2*)(dst + H2 + f) = make_uint2(pk(e.x, e.y), pk(e.z, e.w));
    }
    for (int f = 4 * t; f < HID; f += 1024) {
        float4 h = *(const float4*)(hidden + (size_t)b * HID + f);
        *(uint2*)(dst + K1G + f) = make_uint2(pk(h.x, h.y), pk(h.z, h.w));
    }
}

// ===========================================================================
// fp16 GEMM, tile M64 x N256, K-chunk 16, 8 warps (warp tile 64x32), occ 2.
// grid (mhalf 2, ntile, split). A fp16 pre-packed; B fp32 cvt on the fly.
// mode 0: gates (B = W_ih|W_hh, split-K -> g_gates_part)
// mode 1: fc    (B = W_fc, C = pred + bias)
// ===========================================================================
__global__ __launch_bounds__(256, 2) void gemm_kernel(
    int mode,
    const float* __restrict__ W_ih, const float* __restrict__ W_hh,
    const float* __restrict__ W_fc, const float* __restrict__ b_fc,
    float* __restrict__ pred)
{
    __shared__ __half smb[2 * STG];
    __shared__ float s_bias[256];

    int t = threadIdx.x, warp = t >> 5, lane = t & 31;
    int mhalf = blockIdx.x, nt = blockIdx.y, split = blockIdx.z;

    const __half* Aact = (mode == 0) ? g_act16 : g_h16;
    int lda   = (mode == 0) ? KG : HID;
    int Kbase = (mode == 0) ? split * (KG / GSPLIT) : 0;
    int NC    = (mode == 0) ? (KG / GSPLIT) >> 4 : HID >> 4;

    if (mode == 1) s_bias[t] = b_fc[nt * 256 + t];

    float acc[4][4][4];
    #pragma unroll
    for (int mi = 0; mi < 4; mi++)
        #pragma unroll
        for (int ni = 0; ni < 4; ni++)
            #pragma unroll
            for (int q = 0; q < 4; q++) acc[mi][ni][q] = 0.f;

    int arow = t >> 2, agrp = t & 3;      // A: 64 rows x 4 groups-of-4
    // B: thread t owns row t's 16 k-elems
    uint2  aRaw;
    float4 bRaw[4];

    auto load_chunk = [&](int ch) {
        int k0 = Kbase + (ch << 4);
        aRaw = *(const uint2*)(Aact + (size_t)(mhalf * 64 + arow) * lda + k0 + agrp * 4);
        int rg = nt * 256 + t;
        const float* bp;
        if (mode == 0) bp = (k0 < K1G) ? W_ih + (size_t)rg * K1G + k0
                                       : W_hh + (size_t)rg * HID + (k0 - K1G);
        else           bp = W_fc + (size_t)rg * HID + k0;
        bRaw[0] = ((const float4*)bp)[0];
        bRaw[1] = ((const float4*)bp)[1];
        bRaw[2] = ((const float4*)bp)[2];
        bRaw[3] = ((const float4*)bp)[3];
    };

    auto store_stage = [&](int stg) {
        __half* Ah = smb + stg * STG;
        __half* Bh = Ah + 64 * PADK;
        *(uint2*)(Ah + arow * PADK + agrp * 4) = aRaw;
        uint4 lo = make_uint4(pk(bRaw[0].x, bRaw[0].y), pk(bRaw[0].z, bRaw[0].w),
                              pk(bRaw[1].x, bRaw[1].y), pk(bRaw[1].z, bRaw[1].w));
        uint4 hi = make_uint4(pk(bRaw[2].x, bRaw[2].y), pk(bRaw[2].z, bRaw[2].w),
                              pk(bRaw[3].x, bRaw[3].y), pk(bRaw[3].z, bRaw[3].w));
        *(uint4*)(Bh + t * PADK)     = lo;
        *(uint4*)(Bh + t * PADK + 8) = hi;
    };

    auto mma_stage = [&](int stg) {
        __half* Ah = smb + stg * STG;
        __half* Bh = Ah + 64 * PADK;
        uint32_t bf[4][2];
        #pragma unroll
        for (int nip = 0; nip < 2; nip++) {
            uint32_t r[4];
            int rrow = warp * 32 + nip * 16 + ((lane >> 4) & 1) * 8 + (lane & 7);
            int rcol = ((lane >> 3) & 1) * 8;
            ldm_x4(r, &Bh[rrow * PADK + rcol]);
            bf[nip * 2][0] = r[0]; bf[nip * 2][1] = r[1];
            bf[nip * 2 + 1][0] = r[2]; bf[nip * 2 + 1][1] = r[3];
        }
        #pragma unroll
        for (int mi = 0; mi < 4; mi++) {
            uint32_t ah[4];
            ldm_x4(ah, &Ah[((lane & 15) + mi * 16) * PADK + (lane >> 4) * 8]);
            #pragma unroll
            for (int ni = 0; ni < 4; ni++) mma_f16(acc[mi][ni], ah, bf[ni]);
        }
    };

    load_chunk(0);
    store_stage(0);
    __syncthreads();

    for (int ch = 0; ch < NC; ++ch) {
        int cur = ch & 1;
        if (ch + 1 < NC) load_chunk(ch + 1);    // LDGs in flight during mma
        mma_stage(cur);
        if (ch + 1 < NC) store_stage(cur ^ 1);
        __syncthreads();
    }

    // epilogue
    int r0 = lane >> 2;
    int c0l = (lane & 3) * 2;
    if (mode == 0) {
        float* Cp = g_gates_part + (size_t)split * BATCH * NG;
        #pragma unroll
        for (int mi = 0; mi < 4; mi++)
            #pragma unroll
            for (int ni = 0; ni < 4; ni++) {
                int grow = mhalf * 64 + r0 + mi * 16;
                int gcol = nt * 256 + warp * 32 + ni * 8 + c0l;
                Cp[(size_t)grow * NG + gcol]           = acc[mi][ni][0];
                Cp[(size_t)grow * NG + gcol + 1]       = acc[mi][ni][1];
                Cp[(size_t)(grow + 8) * NG + gcol]     = acc[mi][ni][2];
                Cp[(size_t)(grow + 8) * NG + gcol + 1] = acc[mi][ni][3];
            }
    } else {
        #pragma unroll
        for (int mi = 0; mi < 4; mi++)
            #pragma unroll
            for (int ni = 0; ni < 4; ni++) {
                int grow = mhalf * 64 + r0 + mi * 16;
                int cc   = warp * 32 + ni * 8 + c0l;
                int gcol = nt * 256 + cc;
                float b0 = s_bias[cc], b1 = s_bias[cc + 1];
                pred[(size_t)grow * VOCAB + gcol]           = acc[mi][ni][0] + b0;
                pred[(size_t)grow * VOCAB + gcol + 1]       = acc[mi][ni][1] + b1;
                pred[(size_t)(grow + 8) * VOCAB + gcol]     = acc[mi][ni][2] + b0;
                pred[(size_t)(grow + 8) * VOCAB + gcol + 1] = acc[mi][ni][3] + b1;
            }
    }
}

// ===========================================================================
// LSTM pointwise: sum split-K gate partials + biases -> h_new (fp32+fp16), c_new
// ===========================================================================
__device__ __forceinline__ float sigmf(float v) { return 1.f / (1.f + __expf(-v)); }
__device__ __forceinline__ float tanhfast(float v) { return 1.f - 2.f / (1.f + __expf(2.f * v)); }

__global__ __launch_bounds__(256) void lstm_kernel(
    const float* __restrict__ b_ih, const float* __restrict__ b_hh,
    const float* __restrict__ cell, float* __restrict__ h_out, float* __restrict__ c_out)
{
    int idx = blockIdx.x * 256 + threadIdx.x;
    int b = idx >> 10, j = idx & 1023;
    const float* g = g_gates_part + (size_t)b * NG;
    float gs[4];
    #pragma unroll
    for (int gi = 0; gi < 4; gi++) {
        int col = gi * HID + j;
        float v = b_ih[col] + b_hh[col];
        #pragma unroll
        for (int y = 0; y < GSPLIT; y++) v += g[(size_t)y * BATCH * NG + col];
        gs[gi] = v;
    }
    float ig = sigmf(gs[0]), fg = sigmf(gs[1]);
    float gg = tanhfast(gs[2]), og = sigmf(gs[3]);
    float c = fg * cell[idx] + ig * gg;
    float h = og * tanhfast(c);
    c_out[idx] = c;
    h_out[idx] = h;
    g_h16[idx] = __float2half(h);
}

// ===========================================================================
extern "C" void kernel_launch(void* const* d_in, const int* in_sizes, int n_in,
                              void* d_out, int out_size)
{
    const int*   x      = (const int*)d_in[0];
    const float* enc    = (const float*)d_in[1];
    const float* hidden = (const float*)d_in[2];
    const float* cell   = (const float*)d_in[3];
    const float* emb    = (const float*)d_in[4];
    const float* W_e    = (const float*)d_in[5];
    const float* b_e    = (const float*)d_in[6];
    const float* W_ih   = (const float*)d_in[7];
    const float* W_hh   = (const float*)d_in[8];
    const float* b_ih   = (const float*)d_in[9];
    const float* b_hh   = (const float*)d_in[10];
    const float* W_fc   = (const float*)d_in[11];
    const float* b_fc   = (const float*)d_in[12];

    float* out   = (float*)d_out;
    float* h_out = out + (size_t)BATCH * VOCAB;
    float* c_out = h_out + BATCH * HID;

    static bool attr_set = false;
    if (!attr_set) {
        cudaFuncSetAttribute(attn_kernel, cudaFuncAttributeMaxDynamicSharedMemorySize,
                             ATTN_SMEM);
        attr_set = true;
    }

    attn_kernel<<<dim3(BATCH, ASPLIT), 256, ATTN_SMEM>>>(enc, hidden, W_e, b_e);
    pack_kernel<<<BATCH, 256>>>(x, emb, hidden);
    gemm_kernel<<<dim3(2, NG / 256, GSPLIT), 256>>>(0, W_ih, W_hh, W_fc, b_fc, out);
    lstm_kernel<<<(BATCH * HID) / 256, 256>>>(b_ih, b_hh, cell, h_out, c_out);
    gemm_kernel<<<dim3(2, VOCAB / 256, 1), 256>>>(1, W_ih, W_hh, W_fc, b_fc, out);
}

// round 7
// speedup vs baseline: 1.4757x; 1.4757x over previous
#include <cuda_runtime.h>
#include <cuda_fp16.h>
#include <cstdint>

#define BATCH 128
#define SEQ   512
#define HID   1024
#define H2    2048
#define EMB   512
#define VOCAB 32000
#define KG    3584          /* 2048 ctx + 512 emb + 1024 hidden */
#define NG    4096
#define K1G   2560          /* W_ih K extent */
#define GSPLIT 4
#define PAD   40            /* 80B fp16 row stride -> conflict-free ldmatrix */
#define STG_ELEMS (2 * 128 * PAD)
#define GEMM_SMEM (2 * STG_ELEMS * (int)sizeof(__half))   /* 40KB */

#define ABUF 8192                           /* bytes per staged enc row */
#define ATTN_SMEM (16384 + 8 * 2 * ABUF)    /* w2 + acc + 8 warps x 2 bufs = 144KB */

__device__ __half g_act16[BATCH * KG];      // fp16 [ctx | emb | hidden]
__device__ __half g_h16[BATCH * HID];       // fp16 h_new
__device__ float  g_gates_part[GSPLIT * BATCH * NG];

// ---------------------------------------------------------------------------
__device__ __forceinline__ uint32_t smem_u32(const void* p) {
    return (uint32_t)__cvta_generic_to_shared(p);
}
__device__ __forceinline__ void cpa16(uint32_t dst, const void* src) {
    asm volatile("cp.async.cg.shared.global [%0], [%1], 16;\n" :: "r"(dst), "l"(src));
}
#define CPA_COMMIT() asm volatile("cp.async.commit_group;\n" ::: "memory")
#define CPA_WAIT(n)  asm volatile("cp.async.wait_group %0;\n" :: "n"(n) : "memory")

__device__ __forceinline__ uint32_t pk(float a, float b) {
    __half2 h = __floats2half2_rn(a, b);
    return *reinterpret_cast<uint32_t*>(&h);
}

// ===========================================================================
// attention: 1 CTA / batch elem; 8 warps; warp w owns s = w, w+8, ...
// Per-warp cp.async double-buffered row staging (2 x 8KB smem per warp):
// no register staging, no CTA syncs inside the stream loop.
// No max-shift (energies relu-bounded -> exp safe).
// Writes fp16 [ctx | emb | hidden] row for the gate GEMM.
// ===========================================================================
extern __shared__ char s_dyn[];

__global__ __launch_bounds__(256) void attn_kernel(
    const float* __restrict__ enc, const float* __restrict__ hidden,
    const float* __restrict__ W_e, const float* __restrict__ b_e,
    const int* __restrict__ x, const float* __restrict__ emb_table)
{
    float* s_w2  = (float*)s_dyn;            // 2048 f
    float* s_acc = s_w2 + H2;                // 2048 f
    char*  bufs  = s_dyn + 16384;
    __shared__ float s_red[8], s_z[8];
    __shared__ float s_hb, s_invZ;

    int b = blockIdx.x, t = threadIdx.x;
    int warp = t >> 5, lane = t & 31;

    for (int j = t; j < H2; j += 256) { s_w2[j] = W_e[HID + j]; s_acc[j] = 0.f; }

    // hb = hidden[b] . W_e[0:HID] + b_e
    float p = 0.f;
    for (int j = t; j < HID; j += 256) p += hidden[b * HID + j] * W_e[j];
    #pragma unroll
    for (int o = 16; o > 0; o >>= 1) p += __shfl_xor_sync(0xffffffffu, p, o);
    if (lane == 0) s_red[warp] = p;
    __syncthreads();
    if (t == 0) {
        float s = 0.f;
        #pragma unroll
        for (int i = 0; i < 8; i++) s += s_red[i];
        s_hb = s + b_e[0];
    }
    __syncthreads();
    float hb = s_hb;

    char* myb = bufs + warp * 2 * ABUF;

    auto issue_row = [&](int s, char* dstbuf) {
        const char* src = (const char*)(enc + ((size_t)s * BATCH + b) * H2) + lane * 16;
        uint32_t dst = smem_u32(dstbuf) + lane * 16;
        #pragma unroll
        for (int c = 0; c < 16; c++) cpa16(dst + c * 512, src + c * 512);
        CPA_COMMIT();
    };

    float4 acc[16];
    #pragma unroll
    for (int i = 0; i < 16; i++) acc[i] = make_float4(0.f, 0.f, 0.f, 0.f);
    float Zw = 0.f;

    issue_row(warp, myb);

    const float4* wp = (const float4*)s_w2 + lane;

    #pragma unroll 1
    for (int k = 0; k < SEQ / 8; k++) {
        char* curp = myb + (k & 1) * ABUF;
        if (k + 1 < SEQ / 8) {
            issue_row(warp + 8 * (k + 1), myb + ((k + 1) & 1) * ABUF);
            CPA_WAIT(1);
        } else {
            CPA_WAIT(0);
        }
        __syncwarp();

        const float4* vp = (const float4*)curp + lane;
        float pr = 0.f;
        #pragma unroll
        for (int i = 0; i < 16; i++) {
            float4 v = vp[32 * i];
            float4 w = wp[32 * i];
            pr += v.x * w.x + v.y * w.y + v.z * w.z + v.w * w.w;
        }
        #pragma unroll
        for (int o = 16; o > 0; o >>= 1) pr += __shfl_xor_sync(0xffffffffu, pr, o);
        float wg = __expf(fmaxf(pr + hb, 0.f));
        Zw += wg;
        #pragma unroll
        for (int i = 0; i < 16; i++) {
            float4 v = vp[32 * i];
            acc[i].x += wg * v.x; acc[i].y += wg * v.y;
            acc[i].z += wg * v.z; acc[i].w += wg * v.w;
        }
    }

    // merge warps via smem atomics
    #pragma unroll
    for (int i = 0; i < 16; i++) {
        int c = 4 * (lane + 32 * i);
        atomicAdd(&s_acc[c + 0], acc[i].x);
        atomicAdd(&s_acc[c + 1], acc[i].y);
        atomicAdd(&s_acc[c + 2], acc[i].z);
        atomicAdd(&s_acc[c + 3], acc[i].w);
    }
    if (lane == 0) s_z[warp] = Zw;
    __syncthreads();
    if (t == 0) {
        float z = 0.f;
        #pragma unroll
        for (int i = 0; i < 8; i++) z += s_z[i];
        s_invZ = 1.f / z;
    }
    __syncthreads();
    float iz = s_invZ;

    __half* dst = g_act16 + (size_t)b * KG;
    for (int j = t; j < H2; j += 256) dst[j] = __float2half(s_acc[j] * iz);
    int tok = x[b];
    for (int j = t; j < EMB; j += 256)
        dst[H2 + j] = __float2half(emb_table[(size_t)tok * EMB + j]);
    for (int j = t; j < HID; j += 256)
        dst[K1G + j] = __float2half(hidden[b * HID + j]);
}

// ===========================================================================
// fp16 GEMM (R5-frozen): mma.sync m16n8k16, tile 128x128, K-chunk 32,
// double-buffered smem, 2 CTAs/SM.
// mode 0: gates (B = W_ih|W_hh piecewise, K split GSPLIT ways -> partials)
// mode 1: fc    (B = W_fc, C = pred + bias)
// ===========================================================================
__device__ __forceinline__ void ldm_x4(uint32_t* r, const __half* p) {
    uint32_t a = smem_u32(p);
    asm volatile("ldmatrix.sync.aligned.m8n8.x4.shared.b16 {%0,%1,%2,%3}, [%4];\n"
                 : "=r"(r[0]), "=r"(r[1]), "=r"(r[2]), "=r"(r[3]) : "r"(a));
}
__device__ __forceinline__ void ldm_x2(uint32_t* r, const __half* p) {
    uint32_t a = smem_u32(p);
    asm volatile("ldmatrix.sync.aligned.m8n8.x2.shared.b16 {%0,%1}, [%2];\n"
                 : "=r"(r[0]), "=r"(r[1]) : "r"(a));
}
__device__ __forceinline__ void mma_f16(float* d, const uint32_t* a, const uint32_t* b) {
    asm volatile("mma.sync.aligned.m16n8k16.row.col.f32.f16.f16.f32 "
                 "{%0,%1,%2,%3}, {%4,%5,%6,%7}, {%8,%9}, {%0,%1,%2,%3};\n"
                 : "+f"(d[0]), "+f"(d[1]), "+f"(d[2]), "+f"(d[3])
                 : "r"(a[0]), "r"(a[1]), "r"(a[2]), "r"(a[3]), "r"(b[0]), "r"(b[1]));
}

extern __shared__ __half smb[];

__global__ __launch_bounds__(256, 2) void gemm_kernel(
    int mode,
    const float* __restrict__ W_ih, const float* __restrict__ W_hh,
    const float* __restrict__ W_fc, const float* __restrict__ b_fc,
    float* __restrict__ pred)
{
    __shared__ float s_bias[128];

    int t = threadIdx.x, warp = t >> 5, lane = t & 31;
    int nt = blockIdx.x, split = blockIdx.y;

    const __half* Aact = (mode == 0) ? g_act16 : g_h16;
    int lda   = (mode == 0) ? KG : HID;
    int Kbase = (mode == 0) ? split * (KG / GSPLIT) : 0;
    int NC    = (mode == 0) ? (KG / GSPLIT) >> 5 : HID >> 5;

    if (mode == 1 && t < 128) s_bias[t] = b_fc[nt * 128 + t];

    float acc[4][4][4];
    #pragma unroll
    for (int mi = 0; mi < 4; mi++)
        #pragma unroll
        for (int ni = 0; ni < 4; ni++)
            #pragma unroll
            for (int q = 0; q < 4; q++) acc[mi][ni][q] = 0.f;

    int rw[2], gp[2];
    #pragma unroll
    for (int j = 0; j < 2; j++) { int id = t + j * 256; rw[j] = id >> 2; gp[j] = id & 3; }

    uint4  aS[2];
    float4 bS[2][2];

    auto load_chunk = [&](int ch) {
        #pragma unroll
        for (int j = 0; j < 2; j++) {
            int k = Kbase + (ch << 5) + gp[j] * 8;
            aS[j] = *(const uint4*)(Aact + (size_t)rw[j] * lda + k);
            int rg = nt * 128 + rw[j];
            const float* bp;
            if (mode == 0) bp = (k < K1G) ? W_ih + (size_t)rg * K1G + k
                                          : W_hh + (size_t)rg * HID + (k - K1G);
            else           bp = W_fc + (size_t)rg * HID + k;
            bS[j][0] = ((const float4*)bp)[0];
            bS[j][1] = ((const float4*)bp)[1];
        }
    };

    auto store_stage = [&](int stg) {
        __half* Ah = smb + stg * STG_ELEMS;
        __half* Bh = Ah + 128 * PAD;
        #pragma unroll
        for (int j = 0; j < 2; j++) {
            int off = rw[j] * PAD + gp[j] * 8;
            *(uint4*)(Ah + off) = aS[j];
            uint4 bp16 = make_uint4(pk(bS[j][0].x, bS[j][0].y), pk(bS[j][0].z, bS[j][0].w),
                                    pk(bS[j][1].x, bS[j][1].y), pk(bS[j][1].z, bS[j][1].w));
            *(uint4*)(Bh + off) = bp16;
        }
    };

    int mw = (warp >> 2) * 64, nw = (warp & 3) * 32;

    auto mma_stage = [&](int stg) {
        __half* Ah = smb + stg * STG_ELEMS;
        __half* Bh = Ah + 128 * PAD;
        #pragma unroll
        for (int ks = 0; ks < 2; ks++) {
            uint32_t bh[4][2];
            int br = nw + (lane & 7);
            int bc = ks * 16 + ((lane >> 3) & 1) * 8;
            #pragma unroll
            for (int ni = 0; ni < 4; ni++)
                ldm_x2(bh[ni], &Bh[(br + ni * 8) * PAD + bc]);
            int ar = mw + (lane & 15);
            int ac = ks * 16 + ((lane >> 4) << 3);
            #pragma unroll
            for (int mi = 0; mi < 4; mi++) {
                uint32_t ah[4];
                ldm_x4(ah, &Ah[(ar + mi * 16) * PAD + ac]);
                #pragma unroll
                for (int ni = 0; ni < 4; ni++)
                    mma_f16(acc[mi][ni], ah, bh[ni]);
            }
        }
    };

    load_chunk(0);
    store_stage(0);
    __syncthreads();

    for (int ch = 0; ch < NC; ++ch) {
        int cur = ch & 1;
        if (ch + 1 < NC) load_chunk(ch + 1);
        mma_stage(cur);
        if (ch + 1 < NC) store_stage(cur ^ 1);
        __syncthreads();
    }

    int r0 = mw + (lane >> 2);
    int cb = nw + (lane & 3) * 2;
    if (mode == 0) {
        float* Cp = g_gates_part + (size_t)split * BATCH * NG;
        #pragma unroll
        for (int mi = 0; mi < 4; mi++)
            #pragma unroll
            for (int ni = 0; ni < 4; ni++) {
                int ng0 = nt * 128 + cb + ni * 8;
                int rA  = r0 + mi * 16;
                Cp[(size_t)rA * NG + ng0]           = acc[mi][ni][0];
                Cp[(size_t)rA * NG + ng0 + 1]       = acc[mi][ni][1];
                Cp[(size_t)(rA + 8) * NG + ng0]     = acc[mi][ni][2];
                Cp[(size_t)(rA + 8) * NG + ng0 + 1] = acc[mi][ni][3];
            }
    } else {
        #pragma unroll
        for (int mi = 0; mi < 4; mi++)
            #pragma unroll
            for (int ni = 0; ni < 4; ni++) {
                int c0 = cb + ni * 8;
                int ng0 = nt * 128 + c0;
                int rA  = r0 + mi * 16;
                float b0 = s_bias[c0], b1 = s_bias[c0 + 1];
                pred[(size_t)rA * VOCAB + ng0]           = acc[mi][ni][0] + b0;
                pred[(size_t)rA * VOCAB + ng0 + 1]       = acc[mi][ni][1] + b1;
                pred[(size_t)(rA + 8) * VOCAB + ng0]     = acc[mi][ni][2] + b0;
                pred[(size_t)(rA + 8) * VOCAB + ng0 + 1] = acc[mi][ni][3] + b1;
            }
    }
}

// ===========================================================================
// LSTM pointwise: sum split-K gate partials + biases -> h_new (fp32+fp16), c_new
// ===========================================================================
__device__ __forceinline__ float sigmf(float v) { return 1.f / (1.f + __expf(-v)); }
__device__ __forceinline__ float tanhfast(float v) { return 1.f - 2.f / (1.f + __expf(2.f * v)); }

__global__ __launch_bounds__(256) void lstm_kernel(
    const float* __restrict__ b_ih, const float* __restrict__ b_hh,
    const float* __restrict__ cell, float* __restrict__ h_out, float* __restrict__ c_out)
{
    int idx = blockIdx.x * 256 + threadIdx.x;
    int b = idx >> 10, j = idx & 1023;
    const float* g = g_gates_part + (size_t)b * NG;
    float gs[4];
    #pragma unroll
    for (int gi = 0; gi < 4; gi++) {
        int col = gi * HID + j;
        float v = b_ih[col] + b_hh[col];
        #pragma unroll
        for (int y = 0; y < GSPLIT; y++) v += g[(size_t)y * BATCH * NG + col];
        gs[gi] = v;
    }
    float ig = sigmf(gs[0]), fg = sigmf(gs[1]);
    float gg = tanhfast(gs[2]), og = sigmf(gs[3]);
    float c = fg * cell[idx] + ig * gg;
    float h = og * tanhfast(c);
    c_out[idx] = c;
    h_out[idx] = h;
    g_h16[idx] = __float2half(h);
}

// ===========================================================================
extern "C" void kernel_launch(void* const* d_in, const int* in_sizes, int n_in,
                              void* d_out, int out_size)
{
    const int*   x      = (const int*)d_in[0];
    const float* enc    = (const float*)d_in[1];
    const float* hidden = (const float*)d_in[2];
    const float* cell   = (const float*)d_in[3];
    const float* emb    = (const float*)d_in[4];
    const float* W_e    = (const float*)d_in[5];
    const float* b_e    = (const float*)d_in[6];
    const float* W_ih   = (const float*)d_in[7];
    const float* W_hh   = (const float*)d_in[8];
    const float* b_ih   = (const float*)d_in[9];
    const float* b_hh   = (const float*)d_in[10];
    const float* W_fc   = (const float*)d_in[11];
    const float* b_fc   = (const float*)d_in[12];

    float* out   = (float*)d_out;
    float* h_out = out + (size_t)BATCH * VOCAB;
    float* c_out = h_out + BATCH * HID;

    static bool attr_set = false;
    if (!attr_set) {
        cudaFuncSetAttribute(attn_kernel, cudaFuncAttributeMaxDynamicSharedMemorySize,
                             ATTN_SMEM);
        attr_set = true;
    }

    attn_kernel<<<BATCH, 256, ATTN_SMEM>>>(enc, hidden, W_e, b_e, x, emb);
    gemm_kernel<<<dim3(NG / 128, GSPLIT), 256, GEMM_SMEM>>>(
        0, W_ih, W_hh, W_fc, b_fc, out);
    lstm_kernel<<<(BATCH * HID) / 256, 256>>>(b_ih, b_hh, cell, h_out, c_out);
    gemm_kernel<<<dim3(VOCAB / 128, 1), 256, GEMM_SMEM>>>(
        1, W_ih, W_hh, W_fc, b_fc, out);
}

// round 8
// speedup vs baseline: 1.5404x; 1.0438x over previous
#include <cuda_runtime.h>
#include <cuda_fp16.h>
#include <cstdint>

#define BATCH 128
#define SEQ   512
#define HID   1024
#define H2    2048
#define EMB   512
#define VOCAB 32000
#define KG    3584          /* 2048 ctx + 512 emb + 1024 hidden */
#define NG    4096
#define K1G   2560          /* W_ih K extent */
#define GSPLIT 8
#define PAD   40            /* 80B fp16 row stride -> conflict-free ldmatrix */
#define STG_ELEMS ((128 + 256) * PAD)       /* A(128 rows) + B(256 rows) per stage */
#define GEMM_SMEM (2 * STG_ELEMS * (int)sizeof(__half))   /* 61440 B */

__device__ __half g_act16[BATCH * KG];      // fp16 [ctx | emb | hidden]
__device__ __half g_h16[BATCH * HID];       // fp16 h_new
__device__ float  g_gates_part[GSPLIT * BATCH * NG];

// ===========================================================================
// attention (R5-frozen): 1 CTA / batch elem, one streaming pass, no max-shift
// (energies relu-bounded -> exp safe). Two s-rows register double-buffered,
// W_e read from smem inside the dot. Writes fp16 [ctx | emb | hidden].
// ===========================================================================
__device__ __forceinline__ void attn_step(
    const float4* __restrict__ w2v4, int lane, const float4 v[16],
    float hb, float& Zw, float4 acc[16])
{
    float pr = 0.f;
    #pragma unroll
    for (int i = 0; i < 16; i++) {
        float4 w = w2v4[lane + 32 * i];
        pr += v[i].x * w.x + v[i].y * w.y + v[i].z * w.z + v[i].w * w.w;
    }
    #pragma unroll
    for (int o = 16; o > 0; o >>= 1) pr += __shfl_xor_sync(0xffffffffu, pr, o);
    float wg = __expf(fmaxf(pr + hb, 0.f));
    Zw += wg;
    #pragma unroll
    for (int i = 0; i < 16; i++) {
        acc[i].x += wg * v[i].x; acc[i].y += wg * v[i].y;
        acc[i].z += wg * v[i].z; acc[i].w += wg * v[i].w;
    }
}

__global__ __launch_bounds__(256) void attn_kernel(
    const float* __restrict__ enc, const float* __restrict__ hidden,
    const float* __restrict__ W_e, const float* __restrict__ b_e,
    const int* __restrict__ x, const float* __restrict__ emb_table)
{
    __shared__ float s_w2[H2], s_acc[H2];
    __shared__ float s_red[8], s_z[8];
    __shared__ float s_hb, s_invZ;

    int b = blockIdx.x, t = threadIdx.x;
    int warp = t >> 5, lane = t & 31;

    for (int j = t; j < H2; j += 256) { s_w2[j] = W_e[HID + j]; s_acc[j] = 0.f; }

    float p = 0.f;
    for (int j = t; j < HID; j += 256) p += hidden[b * HID + j] * W_e[j];
    #pragma unroll
    for (int o = 16; o > 0; o >>= 1) p += __shfl_xor_sync(0xffffffffu, p, o);
    if (lane == 0) s_red[warp] = p;
    __syncthreads();
    if (t == 0) {
        float s = 0.f;
        #pragma unroll
        for (int i = 0; i < 8; i++) s += s_red[i];
        s_hb = s + b_e[0];
    }
    __syncthreads();
    float hb = s_hb;

    const float4* w2v4 = (const float4*)s_w2;

    float4 acc[16];
    #pragma unroll
    for (int i = 0; i < 16; i++) acc[i] = make_float4(0.f, 0.f, 0.f, 0.f);
    float Zw = 0.f;

    float4 va[16], vb[16];
    {
        const float4* row = (const float4*)(enc + ((size_t)warp * BATCH + b) * H2);
        #pragma unroll
        for (int i = 0; i < 16; i++) va[i] = row[lane + 32 * i];
    }

    for (int s = warp; s < SEQ; s += 16) {
        {
            const float4* row = (const float4*)(enc + ((size_t)(s + 8) * BATCH + b) * H2);
            #pragma unroll
            for (int i = 0; i < 16; i++) vb[i] = row[lane + 32 * i];
        }
        attn_step(w2v4, lane, va, hb, Zw, acc);
        if (s + 16 < SEQ) {
            const float4* row = (const float4*)(enc + ((size_t)(s + 16) * BATCH + b) * H2);
            #pragma unroll
            for (int i = 0; i < 16; i++) va[i] = row[lane + 32 * i];
        }
        attn_step(w2v4, lane, vb, hb, Zw, acc);
    }

    #pragma unroll
    for (int i = 0; i < 16; i++) {
        int c = 4 * (lane + 32 * i);
        atomicAdd(&s_acc[c + 0], acc[i].x);
        atomicAdd(&s_acc[c + 1], acc[i].y);
        atomicAdd(&s_acc[c + 2], acc[i].z);
        atomicAdd(&s_acc[c + 3], acc[i].w);
    }
    if (lane == 0) s_z[warp] = Zw;
    __syncthreads();
    if (t == 0) {
        float z = 0.f;
        #pragma unroll
        for (int i = 0; i < 8; i++) z += s_z[i];
        s_invZ = 1.f / z;
    }
    __syncthreads();
    float iz = s_invZ;

    __half* dst = g_act16 + (size_t)b * KG;
    for (int j = t; j < H2; j += 256) dst[j] = __float2half(s_acc[j] * iz);
    int tok = x[b];
    for (int j = t; j < EMB; j += 256)
        dst[H2 + j] = __float2half(emb_table[(size_t)tok * EMB + j]);
    for (int j = t; j < K1G - H2 - EMB + HID; j += 256)   /* HID */
        dst[K1G + j] = __float2half(hidden[b * HID + j]);
}

// ===========================================================================
// fp16 GEMM: tile M128 x N256, K-chunk 32, 8 warps (warp tile 64x64),
// double-buffered smem (60KB dyn), occ 1, DRAM-paced.
// mode 0: gates (B = W_ih|W_hh piecewise, K split GSPLIT ways -> partials)
// mode 1: fc    (B = W_fc, C = pred + bias)
// ===========================================================================
__device__ __forceinline__ uint32_t smem_u32(const void* p) {
    return (uint32_t)__cvta_generic_to_shared(p);
}
__device__ __forceinline__ void ldm_x4(uint32_t* r, const __half* p) {
    uint32_t a = smem_u32(p);
    asm volatile("ldmatrix.sync.aligned.m8n8.x4.shared.b16 {%0,%1,%2,%3}, [%4];\n"
                 : "=r"(r[0]), "=r"(r[1]), "=r"(r[2]), "=r"(r[3]) : "r"(a));
}
__device__ __forceinline__ void ldm_x2(uint32_t* r, const __half* p) {
    uint32_t a = smem_u32(p);
    asm volatile("ldmatrix.sync.aligned.m8n8.x2.shared.b16 {%0,%1}, [%2];\n"
                 : "=r"(r[0]), "=r"(r[1]) : "r"(a));
}
__device__ __forceinline__ void mma_f16(float* d, const uint32_t* a, const uint32_t* b) {
    asm volatile("mma.sync.aligned.m16n8k16.row.col.f32.f16.f16.f32 "
                 "{%0,%1,%2,%3}, {%4,%5,%6,%7}, {%8,%9}, {%0,%1,%2,%3};\n"
                 : "+f"(d[0]), "+f"(d[1]), "+f"(d[2]), "+f"(d[3])
                 : "r"(a[0]), "r"(a[1]), "r"(a[2]), "r"(a[3]), "r"(b[0]), "r"(b[1]));
}
__device__ __forceinline__ uint32_t pk(float a, float b) {
    __half2 h = __floats2half2_rn(a, b);
    return *reinterpret_cast<uint32_t*>(&h);
}

extern __shared__ __half smb[];

__global__ __launch_bounds__(256) void gemm_kernel(
    int mode,
    const float* __restrict__ W_ih, const float* __restrict__ W_hh,
    const float* __restrict__ W_fc, const float* __restrict__ b_fc,
    float* __restrict__ pred)
{
    __shared__ float s_bias[256];

    int t = threadIdx.x, warp = t >> 5, lane = t & 31;
    int nt = blockIdx.x, split = blockIdx.y;

    const __half* Aact = (mode == 0) ? g_act16 : g_h16;
    int lda   = (mode == 0) ? KG : HID;
    int Kbase = (mode == 0) ? split * (KG / GSPLIT) : 0;
    int NC    = (mode == 0) ? (KG / GSPLIT) >> 5 : HID >> 5;

    if (mode == 1) s_bias[t] = b_fc[nt * 256 + t];

    float acc[4][8][4];
    #pragma unroll
    for (int mi = 0; mi < 4; mi++)
        #pragma unroll
        for (int ni = 0; ni < 8; ni++)
            #pragma unroll
            for (int q = 0; q < 4; q++) acc[mi][ni][q] = 0.f;

    // A: 128 rows x 4 groups-of-8 = 512 slots, 2 per thread
    int arw[2], agp[2];
    #pragma unroll
    for (int j = 0; j < 2; j++) { int id = t + j * 256; arw[j] = id >> 2; agp[j] = id & 3; }
    // B: 256 rows x 4 groups-of-8 = 1024 slots, 4 per thread
    int brw[4], bgp[4];
    #pragma unroll
    for (int j = 0; j < 4; j++) { int id = t + j * 256; brw[j] = id >> 2; bgp[j] = id & 3; }

    uint4  aS[2];
    float4 bS[4][2];

    auto load_chunk = [&](int ch) {
        #pragma unroll
        for (int j = 0; j < 2; j++) {
            int k = Kbase + (ch << 5) + agp[j] * 8;
            aS[j] = *(const uint4*)(Aact + (size_t)arw[j] * lda + k);
        }
        #pragma unroll
        for (int j = 0; j < 4; j++) {
            int k = Kbase + (ch << 5) + bgp[j] * 8;
            int rg = nt * 256 + brw[j];
            const float* bp;
            if (mode == 0) bp = (k < K1G) ? W_ih + (size_t)rg * K1G + k
                                          : W_hh + (size_t)rg * HID + (k - K1G);
            else           bp = W_fc + (size_t)rg * HID + k;
            bS[j][0] = ((const float4*)bp)[0];
            bS[j][1] = ((const float4*)bp)[1];
        }
    };

    auto store_stage = [&](int stg) {
        __half* Ah = smb + stg * STG_ELEMS;
        __half* Bh = Ah + 128 * PAD;
        #pragma unroll
        for (int j = 0; j < 2; j++)
            *(uint4*)(Ah + arw[j] * PAD + agp[j] * 8) = aS[j];
        #pragma unroll
        for (int j = 0; j < 4; j++) {
            uint4 bp16 = make_uint4(pk(bS[j][0].x, bS[j][0].y), pk(bS[j][0].z, bS[j][0].w),
                                    pk(bS[j][1].x, bS[j][1].y), pk(bS[j][1].z, bS[j][1].w));
            *(uint4*)(Bh + brw[j] * PAD + bgp[j] * 8) = bp16;
        }
    };

    int mw = (warp >> 2) * 64, nw = (warp & 3) * 64;

    auto mma_stage = [&](int stg) {
        __half* Ah = smb + stg * STG_ELEMS;
        __half* Bh = Ah + 128 * PAD;
        #pragma unroll
        for (int ks = 0; ks < 2; ks++) {
            uint32_t bh[8][2];
            int br = nw + (lane & 7);
            int bc = ks * 16 + ((lane >> 3) & 1) * 8;
            #pragma unroll
            for (int ni = 0; ni < 8; ni++)
                ldm_x2(bh[ni], &Bh[(br + ni * 8) * PAD + bc]);
            int ar = mw + (lane & 15);
            int ac = ks * 16 + ((lane >> 4) << 3);
            #pragma unroll
            for (int mi = 0; mi < 4; mi++) {
                uint32_t ah[4];
                ldm_x4(ah, &Ah[(ar + mi * 16) * PAD + ac]);
                #pragma unroll
                for (int ni = 0; ni < 8; ni++)
                    mma_f16(acc[mi][ni], ah, bh[ni]);
            }
        }
    };

    load_chunk(0);
    store_stage(0);
    __syncthreads();

    for (int ch = 0; ch < NC; ++ch) {
        int cur = ch & 1;
        if (ch + 1 < NC) load_chunk(ch + 1);    // LDGs in flight during mma
        mma_stage(cur);
        if (ch + 1 < NC) store_stage(cur ^ 1);
        __syncthreads();
    }

    // epilogue
    int r0 = mw + (lane >> 2);
    int cb = nw + (lane & 3) * 2;
    if (mode == 0) {
        float* Cp = g_gates_part + (size_t)split * BATCH * NG;
        #pragma unroll
        for (int mi = 0; mi < 4; mi++)
            #pragma unroll
            for (int ni = 0; ni < 8; ni++) {
                int ng0 = nt * 256 + cb + ni * 8;
                int rA  = r0 + mi * 16;
                Cp[(size_t)rA * NG + ng0]           = acc[mi][ni][0];
                Cp[(size_t)rA * NG + ng0 + 1]       = acc[mi][ni][1];
                Cp[(size_t)(rA + 8) * NG + ng0]     = acc[mi][ni][2];
                Cp[(size_t)(rA + 8) * NG + ng0 + 1] = acc[mi][ni][3];
            }
    } else {
        #pragma unroll
        for (int mi = 0; mi < 4; mi++)
            #pragma unroll
            for (int ni = 0; ni < 8; ni++) {
                int c0 = cb + ni * 8;
                int ng0 = nt * 256 + c0;
                int rA  = r0 + mi * 16;
                float b0 = s_bias[c0], b1 = s_bias[c0 + 1];
                pred[(size_t)rA * VOCAB + ng0]           = acc[mi][ni][0] + b0;
                pred[(size_t)rA * VOCAB + ng0 + 1]       = acc[mi][ni][1] + b1;
                pred[(size_t)(rA + 8) * VOCAB + ng0]     = acc[mi][ni][2] + b0;
                pred[(size_t)(rA + 8) * VOCAB + ng0 + 1] = acc[mi][ni][3] + b1;
            }
    }
}

// ===========================================================================
// LSTM pointwise: sum split-K gate partials + biases -> h_new (fp32+fp16), c_new
// ===========================================================================
__device__ __forceinline__ float sigmf(float v) { return 1.f / (1.f + __expf(-v)); }
__device__ __forceinline__ float tanhfast(float v) { return 1.f - 2.f / (1.f + __expf(2.f * v)); }

__global__ __launch_bounds__(256) void lstm_kernel(
    const float* __restrict__ b_ih, const float* __restrict__ b_hh,
    const float* __restrict__ cell, float* __restrict__ h_out, float* __restrict__ c_out)
{
    int idx = blockIdx.x * 256 + threadIdx.x;
    int b = idx >> 10, j = idx & 1023;
    const float* g = g_gates_part + (size_t)b * NG;
    float gs[4];
    #pragma unroll
    for (int gi = 0; gi < 4; gi++) {
        int col = gi * HID + j;
        float v = b_ih[col] + b_hh[col];
        #pragma unroll
        for (int y = 0; y < GSPLIT; y++) v += g[(size_t)y * BATCH * NG + col];
        gs[gi] = v;
    }
    float ig = sigmf(gs[0]), fg = sigmf(gs[1]);
    float gg = tanhfast(gs[2]), og = sigmf(gs[3]);
    float c = fg * cell[idx] + ig * gg;
    float h = og * tanhfast(c);
    c_out[idx] = c;
    h_out[idx] = h;
    g_h16[idx] = __float2half(h);
}

// ===========================================================================
extern "C" void kernel_launch(void* const* d_in, const int* in_sizes, int n_in,
                              void* d_out, int out_size)
{
    const int*   x      = (const int*)d_in[0];
    const float* enc    = (const float*)d_in[1];
    const float* hidden = (const float*)d_in[2];
    const float* cell   = (const float*)d_in[3];
    const float* emb    = (const float*)d_in[4];
    const float* W_e    = (const float*)d_in[5];
    const float* b_e    = (const float*)d_in[6];
    const float* W_ih   = (const float*)d_in[7];
    const float* W_hh   = (const float*)d_in[8];
    const float* b_ih   = (const float*)d_in[9];
    const float* b_hh   = (const float*)d_in[10];
    const float* W_fc   = (const float*)d_in[11];
    const float* b_fc   = (const float*)d_in[12];

    float* out   = (float*)d_out;
    float* h_out = out + (size_t)BATCH * VOCAB;
    float* c_out = h_out + BATCH * HID;

    static bool attr_set = false;
    if (!attr_set) {
        cudaFuncSetAttribute(gemm_kernel, cudaFuncAttributeMaxDynamicSharedMemorySize,
                             GEMM_SMEM);
        attr_set = true;
    }

    attn_kernel<<<BATCH, 256>>>(enc, hidden, W_e, b_e, x, emb);
    gemm_kernel<<<dim3(NG / 256, GSPLIT), 256, GEMM_SMEM>>>(
        0, W_ih, W_hh, W_fc, b_fc, out);
    lstm_kernel<<<(BATCH * HID) / 256, 256>>>(b_ih, b_hh, cell, h_out, c_out);
    gemm_kernel<<<dim3(VOCAB / 256, 1), 256, GEMM_SMEM>>>(
        1, W_ih, W_hh, W_fc, b_fc, out);
}

// round 9
// speedup vs baseline: 1.6006x; 1.0391x over previous
#include <cuda_runtime.h>
#include <cuda_fp16.h>
#include <cstdint>

#define BATCH 128
#define SEQ   512
#define HID   1024
#define H2    2048
#define EMB   512
#define VOCAB 32000
#define KG    3584          /* 2048 ctx + 512 emb + 1024 hidden */
#define NG    4096
#define K1G   2560          /* W_ih K extent */
#define GSPLIT 8
#define PADA  40            /* halfs: 80B A row stride, conflict-free ldmatrix */
#define PADB  40            /* floats: 160B B row stride, conflict-free LDS.64 frags */
#define DEPTH 3
#define A_STG_B (128 * PADA * 2)            /* 10240 */
#define B_STG_B (256 * PADB * 4)            /* 40960 */
#define STG_B   (A_STG_B + B_STG_B)         /* 51200 */
#define GEMM_SMEM (DEPTH * STG_B)           /* 153600 */

__device__ __half g_act16[BATCH * KG];      // fp16 [ctx | emb | hidden]
__device__ __half g_h16[BATCH * HID];       // fp16 h_new
__device__ float  g_gates_part[GSPLIT * BATCH * NG];

// ---------------------------------------------------------------------------
__device__ __forceinline__ uint32_t smem_u32(const void* p) {
    return (uint32_t)__cvta_generic_to_shared(p);
}
__device__ __forceinline__ void cpa16(uint32_t dst, const void* src) {
    asm volatile("cp.async.cg.shared.global [%0], [%1], 16;\n" :: "r"(dst), "l"(src));
}
#define CPA_COMMIT() asm volatile("cp.async.commit_group;\n" ::: "memory")
#define CPA_WAIT(n)  asm volatile("cp.async.wait_group %0;\n" :: "n"(n) : "memory")

__device__ __forceinline__ void ldm_x4(uint32_t* r, const __half* p) {
    uint32_t a = smem_u32(p);
    asm volatile("ldmatrix.sync.aligned.m8n8.x4.shared.b16 {%0,%1,%2,%3}, [%4];\n"
                 : "=r"(r[0]), "=r"(r[1]), "=r"(r[2]), "=r"(r[3]) : "r"(a));
}
__device__ __forceinline__ void mma_f16(float* d, const uint32_t* a, const uint32_t* b) {
    asm volatile("mma.sync.aligned.m16n8k16.row.col.f32.f16.f16.f32 "
                 "{%0,%1,%2,%3}, {%4,%5,%6,%7}, {%8,%9}, {%0,%1,%2,%3};\n"
                 : "+f"(d[0]), "+f"(d[1]), "+f"(d[2]), "+f"(d[3])
                 : "r"(a[0]), "r"(a[1]), "r"(a[2]), "r"(a[3]), "r"(b[0]), "r"(b[1]));
}
__device__ __forceinline__ uint32_t pk(float a, float b) {
    __half2 h = __floats2half2_rn(a, b);
    return *reinterpret_cast<uint32_t*>(&h);
}

// ===========================================================================
// attention (frozen): 1 CTA / batch elem, one streaming pass, no max-shift
// (energies relu-bounded -> exp safe). Two s-rows register double-buffered.
// ===========================================================================
__device__ __forceinline__ void attn_step(
    const float4* __restrict__ w2v4, int lane, const float4 v[16],
    float hb, float& Zw, float4 acc[16])
{
    float pr = 0.f;
    #pragma unroll
    for (int i = 0; i < 16; i++) {
        float4 w = w2v4[lane + 32 * i];
        pr += v[i].x * w.x + v[i].y * w.y + v[i].z * w.z + v[i].w * w.w;
    }
    #pragma unroll
    for (int o = 16; o > 0; o >>= 1) pr += __shfl_xor_sync(0xffffffffu, pr, o);
    float wg = __expf(fmaxf(pr + hb, 0.f));
    Zw += wg;
    #pragma unroll
    for (int i = 0; i < 16; i++) {
        acc[i].x += wg * v[i].x; acc[i].y += wg * v[i].y;
        acc[i].z += wg * v[i].z; acc[i].w += wg * v[i].w;
    }
}

__global__ __launch_bounds__(256) void attn_kernel(
    const float* __restrict__ enc, const float* __restrict__ hidden,
    const float* __restrict__ W_e, const float* __restrict__ b_e,
    const int* __restrict__ x, const float* __restrict__ emb_table)
{
    __shared__ float s_w2[H2], s_acc[H2];
    __shared__ float s_red[8], s_z[8];
    __shared__ float s_hb, s_invZ;

    int b = blockIdx.x, t = threadIdx.x;
    int warp = t >> 5, lane = t & 31;

    for (int j = t; j < H2; j += 256) { s_w2[j] = W_e[HID + j]; s_acc[j] = 0.f; }

    float p = 0.f;
    for (int j = t; j < HID; j += 256) p += hidden[b * HID + j] * W_e[j];
    #pragma unroll
    for (int o = 16; o > 0; o >>= 1) p += __shfl_xor_sync(0xffffffffu, p, o);
    if (lane == 0) s_red[warp] = p;
    __syncthreads();
    if (t == 0) {
        float s = 0.f;
        #pragma unroll
        for (int i = 0; i < 8; i++) s += s_red[i];
        s_hb = s + b_e[0];
    }
    __syncthreads();
    float hb = s_hb;

    const float4* w2v4 = (const float4*)s_w2;

    float4 acc[16];
    #pragma unroll
    for (int i = 0; i < 16; i++) acc[i] = make_float4(0.f, 0.f, 0.f, 0.f);
    float Zw = 0.f;

    float4 va[16], vb[16];
    {
        const float4* row = (const float4*)(enc + ((size_t)warp * BATCH + b) * H2);
        #pragma unroll
        for (int i = 0; i < 16; i++) va[i] = row[lane + 32 * i];
    }

    for (int s = warp; s < SEQ; s += 16) {
        {
            const float4* row = (const float4*)(enc + ((size_t)(s + 8) * BATCH + b) * H2);
            #pragma unroll
            for (int i = 0; i < 16; i++) vb[i] = row[lane + 32 * i];
        }
        attn_step(w2v4, lane, va, hb, Zw, acc);
        if (s + 16 < SEQ) {
            const float4* row = (const float4*)(enc + ((size_t)(s + 16) * BATCH + b) * H2);
            #pragma unroll
            for (int i = 0; i < 16; i++) va[i] = row[lane + 32 * i];
        }
        attn_step(w2v4, lane, vb, hb, Zw, acc);
    }

    #pragma unroll
    for (int i = 0; i < 16; i++) {
        int c = 4 * (lane + 32 * i);
        atomicAdd(&s_acc[c + 0], acc[i].x);
        atomicAdd(&s_acc[c + 1], acc[i].y);
        atomicAdd(&s_acc[c + 2], acc[i].z);
        atomicAdd(&s_acc[c + 3], acc[i].w);
    }
    if (lane == 0) s_z[warp] = Zw;
    __syncthreads();
    if (t == 0) {
        float z = 0.f;
        #pragma unroll
        for (int i = 0; i < 8; i++) z += s_z[i];
        s_invZ = 1.f / z;
    }
    __syncthreads();
    float iz = s_invZ;

    __half* dst = g_act16 + (size_t)b * KG;
    for (int j = t; j < H2; j += 256) dst[j] = __float2half(s_acc[j] * iz);
    int tok = x[b];
    for (int j = t; j < EMB; j += 256)
        dst[H2 + j] = __float2half(emb_table[(size_t)tok * EMB + j]);
    for (int j = t; j < HID; j += 256)
        dst[K1G + j] = __float2half(hidden[b * HID + j]);
}

// ===========================================================================
// fp16 GEMM: tile M128 x N256, K-chunk 32, cp.async 3-deep pipeline.
// A fp16 staged via cp.async + ldmatrix; B kept fp32 in smem, fragments
// built directly via 2x LDS.64 + cvt per fragment (layout-verified).
// mode 0: gates (W_ih|W_hh piecewise, split-K -> g_gates_part)
// mode 1: fc    (W_fc, C = pred + bias)
// ===========================================================================
extern __shared__ char smg[];

__global__ __launch_bounds__(256) void gemm_kernel(
    int mode,
    const float* __restrict__ W_ih, const float* __restrict__ W_hh,
    const float* __restrict__ W_fc, const float* __restrict__ b_fc,
    float* __restrict__ pred)
{
    __shared__ float s_bias[256];

    int t = threadIdx.x, warp = t >> 5, lane = t & 31;
    int nt = blockIdx.x, split = blockIdx.y;

    const __half* Aact = (mode == 0) ? g_act16 : g_h16;
    int lda   = (mode == 0) ? KG : HID;
    int Kbase = (mode == 0) ? split * (KG / GSPLIT) : 0;
    int NC    = (mode == 0) ? (KG / GSPLIT) >> 5 : HID >> 5;

    if (mode == 1) s_bias[t] = b_fc[nt * 256 + t];

    float acc[4][8][4];
    #pragma unroll
    for (int mi = 0; mi < 4; mi++)
        #pragma unroll
        for (int ni = 0; ni < 8; ni++)
            #pragma unroll
            for (int q = 0; q < 4; q++) acc[mi][ni][q] = 0.f;

    uint32_t sb = smem_u32(smg);

    auto issue_chunk = [&](int ch) {
        int stg = ch % DEPTH;
        int k0 = Kbase + (ch << 5);
        uint32_t abase = sb + stg * STG_B;
        uint32_t bbase = abase + A_STG_B;
        // A: 128 rows x 4 segs of 16B
        #pragma unroll
        for (int j = 0; j < 2; j++) {
            int id = t + j * 256;
            int row = id >> 2, seg = id & 3;
            cpa16(abase + row * (PADA * 2) + seg * 16,
                  Aact + (size_t)row * lda + k0 + seg * 8);
        }
        // B: 256 rows x 8 segs of 16B (raw fp32)
        const float* wb;
        int ldb, koff;
        if (mode == 0) {
            if (k0 < K1G) { wb = W_ih; ldb = K1G; koff = k0; }
            else          { wb = W_hh; ldb = HID; koff = k0 - K1G; }
        } else            { wb = W_fc; ldb = HID; koff = k0; }
        #pragma unroll
        for (int j = 0; j < 8; j++) {
            int id = t + j * 256;
            int row = id >> 3, seg = id & 7;
            cpa16(bbase + row * (PADB * 4) + seg * 16,
                  wb + (size_t)(nt * 256 + row) * ldb + koff + seg * 4);
        }
        CPA_COMMIT();
    };

    int mw = (warp >> 2) * 64, nw = (warp & 3) * 64;

    auto mma_stage = [&](int stg) {
        const __half* As = (const __half*)(smg + stg * STG_B);
        const float*  Bs = (const float*)(smg + stg * STG_B + A_STG_B);
        #pragma unroll
        for (int ks = 0; ks < 2; ks++) {
            uint32_t ah[4][4];
            int ar = mw + (lane & 15);
            int ac = ks * 16 + (lane >> 4) * 8;
            #pragma unroll
            for (int mi = 0; mi < 4; mi++)
                ldm_x4(ah[mi], &As[(ar + mi * 16) * PADA + ac]);
            int nb = nw + (lane >> 2);
            int kk = ks * 16 + (lane & 3) * 2;
            #pragma unroll
            for (int ni = 0; ni < 8; ni++) {
                const float* bp = &Bs[(nb + ni * 8) * PADB + kk];
                float2 lo = *(const float2*)bp;
                float2 hi = *(const float2*)(bp + 8);
                uint32_t bb[2] = { pk(lo.x, lo.y), pk(hi.x, hi.y) };
                #pragma unroll
                for (int mi = 0; mi < 4; mi++)
                    mma_f16(acc[mi][ni], ah[mi], bb);
            }
        }
    };

    // prologue: fill the pipe
    #pragma unroll
    for (int ch = 0; ch < DEPTH; ch++) {
        if (ch < NC) issue_chunk(ch);
        else         CPA_COMMIT();
    }

    for (int ch = 0; ch < NC; ch++) {
        CPA_WAIT(DEPTH - 1);      // chunk ch landed (this thread)
        __syncthreads();          // cross-thread visibility
        mma_stage(ch % DEPTH);
        __syncthreads();          // all readers done before refill
        if (ch + DEPTH < NC) issue_chunk(ch + DEPTH);
        else                 CPA_COMMIT();
    }

    // epilogue
    int r0 = mw + (lane >> 2);
    int cb = nw + (lane & 3) * 2;
    if (mode == 0) {
        float* Cp = g_gates_part + (size_t)split * BATCH * NG;
        #pragma unroll
        for (int mi = 0; mi < 4; mi++)
            #pragma unroll
            for (int ni = 0; ni < 8; ni++) {
                int ng0 = nt * 256 + cb + ni * 8;
                int rA  = r0 + mi * 16;
                Cp[(size_t)rA * NG + ng0]           = acc[mi][ni][0];
                Cp[(size_t)rA * NG + ng0 + 1]       = acc[mi][ni][1];
                Cp[(size_t)(rA + 8) * NG + ng0]     = acc[mi][ni][2];
                Cp[(size_t)(rA + 8) * NG + ng0 + 1] = acc[mi][ni][3];
            }
    } else {
        #pragma unroll
        for (int mi = 0; mi < 4; mi++)
            #pragma unroll
            for (int ni = 0; ni < 8; ni++) {
                int c0 = cb + ni * 8;
                int ng0 = nt * 256 + c0;
                int rA  = r0 + mi * 16;
                float b0 = s_bias[c0], b1 = s_bias[c0 + 1];
                pred[(size_t)rA * VOCAB + ng0]           = acc[mi][ni][0] + b0;
                pred[(size_t)rA * VOCAB + ng0 + 1]       = acc[mi][ni][1] + b1;
                pred[(size_t)(rA + 8) * VOCAB + ng0]     = acc[mi][ni][2] + b0;
                pred[(size_t)(rA + 8) * VOCAB + ng0 + 1] = acc[mi][ni][3] + b1;
            }
    }
}

// ===========================================================================
// LSTM pointwise: sum split-K gate partials + biases -> h_new (fp32+fp16), c_new
// ===========================================================================
__device__ __forceinline__ float sigmf(float v) { return 1.f / (1.f + __expf(-v)); }
__device__ __forceinline__ float tanhfast(float v) { return 1.f - 2.f / (1.f + __expf(2.f * v)); }

__global__ __launch_bounds__(256) void lstm_kernel(
    const float* __restrict__ b_ih, const float* __restrict__ b_hh,
    const float* __restrict__ cell, float* __restrict__ h_out, float* __restrict__ c_out)
{
    int idx = blockIdx.x * 256 + threadIdx.x;
    int b = idx >> 10, j = idx & 1023;
    const float* g = g_gates_part + (size_t)b * NG;
    float gs[4];
    #pragma unroll
    for (int gi = 0; gi < 4; gi++) {
        int col = gi * HID + j;
        float v = b_ih[col] + b_hh[col];
        #pragma unroll
        for (int y = 0; y < GSPLIT; y++) v += g[(size_t)y * BATCH * NG + col];
        gs[gi] = v;
    }
    float ig = sigmf(gs[0]), fg = sigmf(gs[1]);
    float gg = tanhfast(gs[2]), og = sigmf(gs[3]);
    float c = fg * cell[idx] + ig * gg;
    float h = og * tanhfast(c);
    c_out[idx] = c;
    h_out[idx] = h;
    g_h16[idx] = __float2half(h);
}

// ===========================================================================
extern "C" void kernel_launch(void* const* d_in, const int* in_sizes, int n_in,
                              void* d_out, int out_size)
{
    const int*   x      = (const int*)d_in[0];
    const float* enc    = (const float*)d_in[1];
    const float* hidden = (const float*)d_in[2];
    const float* cell   = (const float*)d_in[3];
    const float* emb    = (const float*)d_in[4];
    const float* W_e    = (const float*)d_in[5];
    const float* b_e    = (const float*)d_in[6];
    const float* W_ih   = (const float*)d_in[7];
    const float* W_hh   = (const float*)d_in[8];
    const float* b_ih   = (const float*)d_in[9];
    const float* b_hh   = (const float*)d_in[10];
    const float* W_fc   = (const float*)d_in[11];
    const float* b_fc   = (const float*)d_in[12];

    float* out   = (float*)d_out;
    float* h_out = out + (size_t)BATCH * VOCAB;
    float* c_out = h_out + BATCH * HID;

    static bool attr_set = false;
    if (!attr_set) {
        cudaFuncSetAttribute(gemm_kernel, cudaFuncAttributeMaxDynamicSharedMemorySize,
                             GEMM_SMEM);
        attr_set = true;
    }

    attn_kernel<<<BATCH, 256>>>(enc, hidden, W_e, b_e, x, emb);
    gemm_kernel<<<dim3(NG / 256, GSPLIT), 256, GEMM_SMEM>>>(
        0, W_ih, W_hh, W_fc, b_fc, out);
    lstm_kernel<<<(BATCH * HID) / 256, 256>>>(b_ih, b_hh, cell, h_out, c_out);
    gemm_kernel<<<dim3(VOCAB / 256, 1), 256, GEMM_SMEM>>>(
        1, W_ih, W_hh, W_fc, b_fc, out);
}

// round 10
// speedup vs baseline: 1.6276x; 1.0169x over previous
#include <cuda_runtime.h>
#include <cuda_fp16.h>
#include <cstdint>

#define BATCH 128
#define SEQ   512
#define HID   1024
#define H2    2048
#define EMB   512
#define VOCAB 32000
#define KG    3584          /* 2048 ctx + 512 emb + 1024 hidden */
#define NG    4096
#define K1G   2560          /* W_ih K extent */
#define GSPLIT 8
#define PADA  40            /* halfs: 80B A row stride, conflict-free ldmatrix */
#define PADB  40            /* floats: 160B B row stride */
#define DEPTH 3
#define A_STG_B (128 * PADA * 2)            /* 10240 */
#define B_STG_B (128 * PADB * 4)            /* 20480 */
#define STG_B   (A_STG_B + B_STG_B)         /* 30720 */
#define GEMM_SMEM (DEPTH * STG_B)           /* 92160 -> 2 CTAs/SM */

__device__ __half g_act16[BATCH * KG];      // fp16 [ctx | emb | hidden]
__device__ __half g_h16[BATCH * HID];       // fp16 h_new
__device__ float  g_gates_part[GSPLIT * BATCH * NG];

// ---------------------------------------------------------------------------
__device__ __forceinline__ uint32_t smem_u32(const void* p) {
    return (uint32_t)__cvta_generic_to_shared(p);
}
__device__ __forceinline__ void cpa16(uint32_t dst, const void* src) {
    asm volatile("cp.async.cg.shared.global [%0], [%1], 16;\n" :: "r"(dst), "l"(src));
}
#define CPA_COMMIT() asm volatile("cp.async.commit_group;\n" ::: "memory")
#define CPA_WAIT(n)  asm volatile("cp.async.wait_group %0;\n" :: "n"(n) : "memory")

__device__ __forceinline__ void ldm_x4(uint32_t* r, const __half* p) {
    uint32_t a = smem_u32(p);
    asm volatile("ldmatrix.sync.aligned.m8n8.x4.shared.b16 {%0,%1,%2,%3}, [%4];\n"
                 : "=r"(r[0]), "=r"(r[1]), "=r"(r[2]), "=r"(r[3]) : "r"(a));
}
__device__ __forceinline__ void mma_f16(float* d, const uint32_t* a, const uint32_t* b) {
    asm volatile("mma.sync.aligned.m16n8k16.row.col.f32.f16.f16.f32 "
                 "{%0,%1,%2,%3}, {%4,%5,%6,%7}, {%8,%9}, {%0,%1,%2,%3};\n"
                 : "+f"(d[0]), "+f"(d[1]), "+f"(d[2]), "+f"(d[3])
                 : "r"(a[0]), "r"(a[1]), "r"(a[2]), "r"(a[3]), "r"(b[0]), "r"(b[1]));
}
__device__ __forceinline__ uint32_t pk(float a, float b) {
    __half2 h = __floats2half2_rn(a, b);
    return *reinterpret_cast<uint32_t*>(&h);
}

// ===========================================================================
// attention (frozen): 1 CTA / batch elem, one streaming pass, no max-shift
// (energies relu-bounded -> exp safe). Two s-rows register double-buffered.
// ===========================================================================
__device__ __forceinline__ void attn_step(
    const float4* __restrict__ w2v4, int lane, const float4 v[16],
    float hb, float& Zw, float4 acc[16])
{
    float pr = 0.f;
    #pragma unroll
    for (int i = 0; i < 16; i++) {
        float4 w = w2v4[lane + 32 * i];
        pr += v[i].x * w.x + v[i].y * w.y + v[i].z * w.z + v[i].w * w.w;
    }
    #pragma unroll
    for (int o = 16; o > 0; o >>= 1) pr += __shfl_xor_sync(0xffffffffu, pr, o);
    float wg = __expf(fmaxf(pr + hb, 0.f));
    Zw += wg;
    #pragma unroll
    for (int i = 0; i < 16; i++) {
        acc[i].x += wg * v[i].x; acc[i].y += wg * v[i].y;
        acc[i].z += wg * v[i].z; acc[i].w += wg * v[i].w;
    }
}

__global__ __launch_bounds__(256) void attn_kernel(
    const float* __restrict__ enc, const float* __restrict__ hidden,
    const float* __restrict__ W_e, const float* __restrict__ b_e,
    const int* __restrict__ x, const float* __restrict__ emb_table)
{
    __shared__ float s_w2[H2], s_acc[H2];
    __shared__ float s_red[8], s_z[8];
    __shared__ float s_hb, s_invZ;

    int b = blockIdx.x, t = threadIdx.x;
    int warp = t >> 5, lane = t & 31;

    for (int j = t; j < H2; j += 256) { s_w2[j] = W_e[HID + j]; s_acc[j] = 0.f; }

    float p = 0.f;
    for (int j = t; j < HID; j += 256) p += hidden[b * HID + j] * W_e[j];
    #pragma unroll
    for (int o = 16; o > 0; o >>= 1) p += __shfl_xor_sync(0xffffffffu, p, o);
    if (lane == 0) s_red[warp] = p;
    __syncthreads();
    if (t == 0) {
        float s = 0.f;
        #pragma unroll
        for (int i = 0; i < 8; i++) s += s_red[i];
        s_hb = s + b_e[0];
    }
    __syncthreads();
    float hb = s_hb;

    const float4* w2v4 = (const float4*)s_w2;

    float4 acc[16];
    #pragma unroll
    for (int i = 0; i < 16; i++) acc[i] = make_float4(0.f, 0.f, 0.f, 0.f);
    float Zw = 0.f;

    float4 va[16], vb[16];
    {
        const float4* row = (const float4*)(enc + ((size_t)warp * BATCH + b) * H2);
        #pragma unroll
        for (int i = 0; i < 16; i++) va[i] = row[lane + 32 * i];
    }

    for (int s = warp; s < SEQ; s += 16) {
        {
            const float4* row = (const float4*)(enc + ((size_t)(s + 8) * BATCH + b) * H2);
            #pragma unroll
            for (int i = 0; i < 16; i++) vb[i] = row[lane + 32 * i];
        }
        attn_step(w2v4, lane, va, hb, Zw, acc);
        if (s + 16 < SEQ) {
            const float4* row = (const float4*)(enc + ((size_t)(s + 16) * BATCH + b) * H2);
            #pragma unroll
            for (int i = 0; i < 16; i++) va[i] = row[lane + 32 * i];
        }
        attn_step(w2v4, lane, vb, hb, Zw, acc);
    }

    #pragma unroll
    for (int i = 0; i < 16; i++) {
        int c = 4 * (lane + 32 * i);
        atomicAdd(&s_acc[c + 0], acc[i].x);
        atomicAdd(&s_acc[c + 1], acc[i].y);
        atomicAdd(&s_acc[c + 2], acc[i].z);
        atomicAdd(&s_acc[c + 3], acc[i].w);
    }
    if (lane == 0) s_z[warp] = Zw;
    __syncthreads();
    if (t == 0) {
        float z = 0.f;
        #pragma unroll
        for (int i = 0; i < 8; i++) z += s_z[i];
        s_invZ = 1.f / z;
    }
    __syncthreads();
    float iz = s_invZ;

    __half* dst = g_act16 + (size_t)b * KG;
    for (int j = t; j < H2; j += 256) dst[j] = __float2half(s_acc[j] * iz);
    int tok = x[b];
    for (int j = t; j < EMB; j += 256)
        dst[H2 + j] = __float2half(emb_table[(size_t)tok * EMB + j]);
    for (int j = t; j < HID; j += 256)
        dst[K1G + j] = __float2half(hidden[b * HID + j]);
}

// ===========================================================================
// fp16 GEMM: tile M128 x N128, K-chunk 32, cp.async 3-stage / 2-ahead
// pipeline (ONE sync per chunk), 2 CTAs/SM.
// A fp16 via cp.async + ldmatrix; B raw fp32 in smem, fragments built by
// 2x LDS.64 + cvt (layout carried over from R9, verified by rel_err).
// mode 0: gates (W_ih|W_hh piecewise, split-K -> g_gates_part)
// mode 1: fc    (W_fc, C = pred + bias)
// ===========================================================================
extern __shared__ char smg[];

__global__ __launch_bounds__(256, 2) void gemm_kernel(
    int mode,
    const float* __restrict__ W_ih, const float* __restrict__ W_hh,
    const float* __restrict__ W_fc, const float* __restrict__ b_fc,
    float* __restrict__ pred)
{
    __shared__ float s_bias[128];

    int t = threadIdx.x, warp = t >> 5, lane = t & 31;
    int nt = blockIdx.x, split = blockIdx.y;

    const __half* Aact = (mode == 0) ? g_act16 : g_h16;
    int lda   = (mode == 0) ? KG : HID;
    int Kbase = (mode == 0) ? split * (KG / GSPLIT) : 0;
    int NC    = (mode == 0) ? (KG / GSPLIT) >> 5 : HID >> 5;

    if (mode == 1 && t < 128) s_bias[t] = b_fc[nt * 128 + t];

    float acc[4][4][4];
    #pragma unroll
    for (int mi = 0; mi < 4; mi++)
        #pragma unroll
        for (int ni = 0; ni < 4; ni++)
            #pragma unroll
            for (int q = 0; q < 4; q++) acc[mi][ni][q] = 0.f;

    uint32_t sb = smem_u32(smg);

    auto issue_chunk = [&](int ch) {
        int stg = ch % DEPTH;
        int k0 = Kbase + (ch << 5);
        uint32_t abase = sb + stg * STG_B;
        uint32_t bbase = abase + A_STG_B;
        // A: 128 rows x 4 segs of 16B = 512 slots, 2 per thread
        #pragma unroll
        for (int j = 0; j < 2; j++) {
            int id = t + j * 256;
            int row = id >> 2, seg = id & 3;
            cpa16(abase + row * (PADA * 2) + seg * 16,
                  Aact + (size_t)row * lda + k0 + seg * 8);
        }
        // B: 128 rows x 8 segs of 16B (raw fp32) = 1024 slots, 4 per thread
        const float* wb;
        int ldb, koff;
        if (mode == 0) {
            if (k0 < K1G) { wb = W_ih; ldb = K1G; koff = k0; }
            else          { wb = W_hh; ldb = HID; koff = k0 - K1G; }
        } else            { wb = W_fc; ldb = HID; koff = k0; }
        #pragma unroll
        for (int j = 0; j < 4; j++) {
            int id = t + j * 256;
            int row = id >> 3, seg = id & 7;
            cpa16(bbase + row * (PADB * 4) + seg * 16,
                  wb + (size_t)(nt * 128 + row) * ldb + koff + seg * 4);
        }
        CPA_COMMIT();
    };

    int mw = (warp >> 2) * 64, nw = (warp & 3) * 32;

    auto mma_stage = [&](int stg) {
        const __half* As = (const __half*)(smg + stg * STG_B);
        const float*  Bs = (const float*)(smg + stg * STG_B + A_STG_B);
        #pragma unroll
        for (int ks = 0; ks < 2; ks++) {
            uint32_t ah[4][4];
            int ar = mw + (lane & 15);
            int ac = ks * 16 + (lane >> 4) * 8;
            #pragma unroll
            for (int mi = 0; mi < 4; mi++)
                ldm_x4(ah[mi], &As[(ar + mi * 16) * PADA + ac]);
            int nb = nw + (lane >> 2);
            int kk = ks * 16 + (lane & 3) * 2;
            #pragma unroll
            for (int ni = 0; ni < 4; ni++) {
                const float* bp = &Bs[(nb + ni * 8) * PADB + kk];
                float2 lo = *(const float2*)bp;
                float2 hi = *(const float2*)(bp + 8);
                uint32_t bb[2] = { pk(lo.x, lo.y), pk(hi.x, hi.y) };
                #pragma unroll
                for (int mi = 0; mi < 4; mi++)
                    mma_f16(acc[mi][ni], ah[mi], bb);
            }
        }
    };

    // prologue: 2 chunks in flight
    issue_chunk(0);
    issue_chunk(1);

    for (int ch = 0; ch < NC; ch++) {
        CPA_WAIT(1);              // chunk ch landed (this thread)
        __syncthreads();          // cross-thread visibility; frees stage (ch+2)%3
        if (ch + 2 < NC) issue_chunk(ch + 2);   // overlaps with mma below
        else             CPA_COMMIT();
        mma_stage(ch % DEPTH);
    }

    // epilogue
    int r0 = mw + (lane >> 2);
    int cb = nw + (lane & 3) * 2;
    if (mode == 0) {
        float* Cp = g_gates_part + (size_t)split * BATCH * NG;
        #pragma unroll
        for (int mi = 0; mi < 4; mi++)
            #pragma unroll
            for (int ni = 0; ni < 4; ni++) {
                int ng0 = nt * 128 + cb + ni * 8;
                int rA  = r0 + mi * 16;
                Cp[(size_t)rA * NG + ng0]           = acc[mi][ni][0];
                Cp[(size_t)rA * NG + ng0 + 1]       = acc[mi][ni][1];
                Cp[(size_t)(rA + 8) * NG + ng0]     = acc[mi][ni][2];
                Cp[(size_t)(rA + 8) * NG + ng0 + 1] = acc[mi][ni][3];
            }
    } else {
        #pragma unroll
        for (int mi = 0; mi < 4; mi++)
            #pragma unroll
            for (int ni = 0; ni < 4; ni++) {
                int c0 = cb + ni * 8;
                int ng0 = nt * 128 + c0;
                int rA  = r0 + mi * 16;
                float b0 = s_bias[c0], b1 = s_bias[c0 + 1];
                pred[(size_t)rA * VOCAB + ng0]           = acc[mi][ni][0] + b0;
                pred[(size_t)rA * VOCAB + ng0 + 1]       = acc[mi][ni][1] + b1;
                pred[(size_t)(rA + 8) * VOCAB + ng0]     = acc[mi][ni][2] + b0;
                pred[(size_t)(rA + 8) * VOCAB + ng0 + 1] = acc[mi][ni][3] + b1;
            }
    }
}

// ===========================================================================
// LSTM pointwise: sum split-K gate partials + biases -> h_new (fp32+fp16), c_new
// ===========================================================================
__device__ __forceinline__ float sigmf(float v) { return 1.f / (1.f + __expf(-v)); }
__device__ __forceinline__ float tanhfast(float v) { return 1.f - 2.f / (1.f + __expf(2.f * v)); }

__global__ __launch_bounds__(256) void lstm_kernel(
    const float* __restrict__ b_ih, const float* __restrict__ b_hh,
    const float* __restrict__ cell, float* __restrict__ h_out, float* __restrict__ c_out)
{
    int idx = blockIdx.x * 256 + threadIdx.x;
    int b = idx >> 10, j = idx & 1023;
    const float* g = g_gates_part + (size_t)b * NG;
    float gs[4];
    #pragma unroll
    for (int gi = 0; gi < 4; gi++) {
        int col = gi * HID + j;
        float v = b_ih[col] + b_hh[col];
        #pragma unroll
        for (int y = 0; y < GSPLIT; y++) v += g[(size_t)y * BATCH * NG + col];
        gs[gi] = v;
    }
    float ig = sigmf(gs[0]), fg = sigmf(gs[1]);
    float gg = tanhfast(gs[2]), og = sigmf(gs[3]);
    float c = fg * cell[idx] + ig * gg;
    float h = og * tanhfast(c);
    c_out[idx] = c;
    h_out[idx] = h;
    g_h16[idx] = __float2half(h);
}

// ===========================================================================
extern "C" void kernel_launch(void* const* d_in, const int* in_sizes, int n_in,
                              void* d_out, int out_size)
{
    const int*   x      = (const int*)d_in[0];
    const float* enc    = (const float*)d_in[1];
    const float* hidden = (const float*)d_in[2];
    const float* cell   = (const float*)d_in[3];
    const float* emb    = (const float*)d_in[4];
    const float* W_e    = (const float*)d_in[5];
    const float* b_e    = (const float*)d_in[6];
    const float* W_ih   = (const float*)d_in[7];
    const float* W_hh   = (const float*)d_in[8];
    const float* b_ih   = (const float*)d_in[9];
    const float* b_hh   = (const float*)d_in[10];
    const float* W_fc   = (const float*)d_in[11];
    const float* b_fc   = (const float*)d_in[12];

    float* out   = (float*)d_out;
    float* h_out = out + (size_t)BATCH * VOCAB;
    float* c_out = h_out + BATCH * HID;

    static bool attr_set = false;
    if (!attr_set) {
        cudaFuncSetAttribute(gemm_kernel, cudaFuncAttributeMaxDynamicSharedMemorySize,
                             GEMM_SMEM);
        attr_set = true;
    }

    attn_kernel<<<BATCH, 256>>>(enc, hidden, W_e, b_e, x, emb);
    gemm_kernel<<<dim3(NG / 128, GSPLIT), 256, GEMM_SMEM>>>(
        0, W_ih, W_hh, W_fc, b_fc, out);
    lstm_kernel<<<(BATCH * HID) / 256, 256>>>(b_ih, b_hh, cell, h_out, c_out);
    gemm_kernel<<<dim3(VOCAB / 128, 1), 256, GEMM_SMEM>>>(
        1, W_ih, W_hh, W_fc, b_fc, out);
}